// round 7
// baseline (speedup 1.0000x reference)
#include <cuda_runtime.h>
#include <cstdint>
#include <math.h>

// ---------------- problem constants ----------------
#define NGEN 10
#define BSZ  4096
#define INDIM 512
#define DIM  1024
#define MAX_TILES 48

// ---------------- scratch ----------------
__device__ float g_x [BSZ * INDIM];
__device__ float g_s1[BSZ * DIM];
__device__ float g_s2[BSZ * DIM];
__device__ int   g_perm[BSZ];
__device__ int   g_tile_genre[MAX_TILES];
__device__ int   g_tile_start[MAX_TILES];
__device__ int   g_tile_rows [MAX_TILES];
__device__ int   g_tile_count;

// ---------------- helpers ----------------
__device__ __forceinline__ unsigned f2tf(float x) {
    unsigned r;
    asm("cvt.rna.tf32.f32 %0, %1;" : "=r"(r) : "f"(x));
    return r;
}
__device__ __forceinline__ float tfr(float x) {   // round-to-tf32, as float bits
    return __uint_as_float(f2tf(x));
}
__device__ __forceinline__ float gelu_f(float x) {
    return 0.5f * x * (1.0f + erff(x * 0.70710678118654752f));
}

// ---------------- reparameterized sample (tf32-rounded output) -------------
__global__ void noise_kernel(const float4* __restrict__ mu,
                             const float4* __restrict__ sig,
                             const float4* __restrict__ z,
                             const int* __restrict__ genre,
                             float4* __restrict__ x) {
    const int C4 = INDIM / 4;
    int i = blockIdx.x * blockDim.x + threadIdx.x;
    if (i >= BSZ * C4) return;
    int row = i / C4, c = i - row * C4;
    int g = genre[row];
    float4 m = mu[g * C4 + c];
    float4 s = sig[g * C4 + c];
    float4 zz = z[i];
    float4 o;
    o.x = tfr(m.x + (fabsf(s.x) + 1e-8f) * zz.x);
    o.y = tfr(m.y + (fabsf(s.y) + 1e-8f) * zz.y);
    o.z = tfr(m.z + (fabsf(s.z) + 1e-8f) * zz.z);
    o.w = tfr(m.w + (fabsf(s.w) + 1e-8f) * zz.w);
    x[i] = o;
}

// ---------------- grouping ----------------
__global__ void group_kernel(const int* __restrict__ genre) {
    __shared__ int cnt[256 * NGEN];
    __shared__ int tot[NGEN];
    __shared__ int base[NGEN];
    int t = threadIdx.x;
    const int per = BSZ / 256;

    int lc[NGEN];
#pragma unroll
    for (int g = 0; g < NGEN; g++) lc[g] = 0;
    int gr[per];
    for (int i = 0; i < per; i++) {
        int g = genre[t * per + i];
        gr[i] = g;
        lc[g]++;
    }
    for (int g = 0; g < NGEN; g++) cnt[t * NGEN + g] = lc[g];
    __syncthreads();

    if (t < NGEN) {
        int s = 0;
        for (int tt = 0; tt < 256; tt++) {
            int v = cnt[tt * NGEN + t];
            cnt[tt * NGEN + t] = s;
            s += v;
        }
        tot[t] = s;
    }
    __syncthreads();

    if (t == 0) {
        int off = 0;
        for (int g = 0; g < NGEN; g++) { base[g] = off; off += tot[g]; }
        int T = 0;
        for (int g = 0; g < NGEN; g++) {
            int c = tot[g], s0 = base[g];
            while (c > 0) {
                g_tile_genre[T] = g;
                g_tile_start[T] = s0;
                g_tile_rows[T]  = c < 128 ? c : 128;
                s0 += 128; c -= 128; T++;
            }
        }
        g_tile_count = T;
    }
    __syncthreads();

    int run[NGEN];
#pragma unroll
    for (int g = 0; g < NGEN; g++) run[g] = cnt[t * NGEN + g];
    for (int i = 0; i < per; i++) {
        int g = gr[i];
        int pos = base[g] + run[g]++;
        g_perm[pos] = t * per + i;
    }
}

// ---------------- TF32 mma.sync GEMM: BN=128, 2 CTAs/SM ----------
// A arrives pre-rounded to tf32 (producers round) -> no cvt in A staging.
constexpr int BM = 128, BN = 128, BK = 32, TPB = 256;
constexpr int A_ST = 4096;
constexpr int SB   = 136;
constexpr int B_ST = BK * SB;              // 4352
constexpr int B0   = 2 * A_ST;             // 8192
constexpr int BIAS = B0 + 2 * B_ST;        // 16896
constexpr int SMEM_WORDS = BIAS + BN;      // 17024
constexpr int SMEM_BYTES = SMEM_WORDS * 4; // 68096

template<bool EXPERT, bool GATHER_A, bool SCATTER_C, bool GELU>
__global__ void __launch_bounds__(TPB, 2)
gemm_tf32(const float* __restrict__ A, const float* __restrict__ Bw,
          const float* __restrict__ bias, float* __restrict__ C,
          int N, int K,
          const int* __restrict__ perm,
          const int* __restrict__ tgen, const int* __restrict__ tstart,
          const int* __restrict__ trows, const int* __restrict__ tcnt)
{
    extern __shared__ float sm[];

    int m0, rows, genre = 0;
    if (EXPERT) {
        if ((int)blockIdx.x >= *tcnt) return;
        genre = tgen[blockIdx.x];
        m0    = tstart[blockIdx.x];
        rows  = trows[blockIdx.x];
    } else {
        m0 = blockIdx.x * BM;
        rows = BM;
    }
    const int n0 = blockIdx.y * BN;
    const float* Bsel = EXPERT ? Bw + (size_t)genre * K * N : Bw;
    const float* bsel = EXPERT ? bias + genre * N : bias;

    const int tid = threadIdx.x;
    if (tid < BN) sm[BIAS + tid] = bsel[n0 + tid];

    // ---- A loader: 4 float4/thread (row0+32i, fixed 4-float seg) ----
    const int row0 = tid >> 3;
    const int seg  = tid & 7;
    const float* aG[4];
#pragma unroll
    for (int i = 0; i < 4; i++) {
        int r = row0 + 32 * i;
        int lrc = r < rows ? r : (rows - 1);
        int src = m0 + lrc;
        if (GATHER_A) src = perm[src];
        aG[i] = A + (size_t)src * K + seg * 4;
    }
    const int aw0 = (seg >> 1) * 1024 + (row0 >> 4) * 128 + ((row0 >> 3) & 1) + 2 * (seg & 1);
    const int grpR = row0 & 7, hR = (row0 >> 1) & 3;
    int awQ[4];
#pragma unroll
    for (int q = 0; q < 4; q++) awQ[q] = (grpR * 4 + (q ^ hR)) * 4;

    // ---- B loader: 4 float4/thread ----
    const float* bG[4];
    int bw[4];
#pragma unroll
    for (int j = 0; j < 4; j++) {
        int v = tid + TPB * j;
        int kB = v >> 5, n4 = v & 31;
        bG[j] = Bsel + (size_t)kB * N + n0 + n4 * 4;
        bw[j] = kB * SB + n4 * 4;
    }

    const int nk = K / BK;

    // ---- prologue: chunk 0 ----
    {
#pragma unroll
        for (int i = 0; i < 4; i++) {
            float4 v = *(const float4*)(aG[i]);
            int ab = aw0 + 256 * i;
            sm[ab + awQ[0]] = v.x;
            sm[ab + awQ[1]] = v.y;
            sm[ab + awQ[2]] = v.z;
            sm[ab + awQ[3]] = v.w;
        }
#pragma unroll
        for (int j = 0; j < 4; j++) {
            float4 v = *(const float4*)(bG[j]);
            uint4 u = make_uint4(f2tf(v.x), f2tf(v.y), f2tf(v.z), f2tf(v.w));
            *(uint4*)(sm + B0 + bw[j]) = u;
        }
    }
    __syncthreads();

    // ---- compute mapping: 8 warps, warp tile 64x32 ----
    const int wid = tid >> 5, lane = tid & 31;
    const int wm = (wid >> 2) * 64;          // 0 / 64
    const int wn = (wid & 3) * 32;           // 0..96
    const int grp = lane >> 2, qid = lane & 3;
    const int chunkOff = (grp * 4 + (qid ^ ((grp >> 1) & 3))) * 4;
    const int mtBase = wm >> 4;              // 0 or 4

    // per-mt activity (uniform per warp; folds to true for non-expert)
    bool mAct[4];
#pragma unroll
    for (int mt = 0; mt < 4; mt++) mAct[mt] = (wm + mt * 16) < rows;

    float acc[4][4][4];
#pragma unroll
    for (int i = 0; i < 4; i++)
#pragma unroll
        for (int j = 0; j < 4; j++)
#pragma unroll
            for (int q = 0; q < 4; q++) acc[i][j][q] = 0.f;

    for (int kt = 0; kt < nk; kt++) {
        const int Ab = (kt & 1) * A_ST;
        const int Bb = B0 + (kt & 1) * B_ST;
        const int Anx = (~kt & 1) * A_ST;
        const int Bnx = B0 + (~kt & 1) * B_ST;
        const bool pf = (kt + 1 < nk);
        const int ko = (kt + 1) * BK;
        float4 av0, av1, bv0, bv1;
        if (pf) {
            av0 = *(const float4*)(aG[0] + ko);
            av1 = *(const float4*)(aG[1] + ko);
            bv0 = *(const float4*)(bG[0] + (size_t)ko * N);
            bv1 = *(const float4*)(bG[1] + (size_t)ko * N);
        }
#pragma unroll
        for (int ks = 0; ks < 4; ks++) {
            uint4 af[4];
            unsigned bfr[4][2];
#pragma unroll
            for (int mt = 0; mt < 4; mt++)
                if (mAct[mt])
                    af[mt] = *(const uint4*)(sm + Ab + ks * 1024 + (mtBase + mt) * 128 + chunkOff);
#pragma unroll
            for (int nt = 0; nt < 4; nt++) {
                int col = wn + nt * 8 + grp;
                bfr[nt][0] = __float_as_uint(sm[Bb + (ks * 8 + qid) * SB + col]);
                bfr[nt][1] = __float_as_uint(sm[Bb + (ks * 8 + qid + 4) * SB + col]);
            }
#pragma unroll
            for (int mt = 0; mt < 4; mt++) {
                if (!mAct[mt]) continue;
#pragma unroll
                for (int nt = 0; nt < 4; nt++) {
                    float* d = acc[mt][nt];
                    asm volatile(
                        "mma.sync.aligned.m16n8k8.row.col.f32.tf32.tf32.f32 "
                        "{%0,%1,%2,%3},{%4,%5,%6,%7},{%8,%9},{%0,%1,%2,%3};\n"
                        : "+f"(d[0]), "+f"(d[1]), "+f"(d[2]), "+f"(d[3])
                        : "r"(af[mt].x), "r"(af[mt].y), "r"(af[mt].z), "r"(af[mt].w),
                          "r"(bfr[nt][0]), "r"(bfr[nt][1]));
                }
            }
            if (ks == 1 && pf) {
                // stage first halves; fetch second halves
                {
                    int ab = Anx + aw0;
                    sm[ab + awQ[0]] = av0.x;
                    sm[ab + awQ[1]] = av0.y;
                    sm[ab + awQ[2]] = av0.z;
                    sm[ab + awQ[3]] = av0.w;
                    ab = Anx + aw0 + 256;
                    sm[ab + awQ[0]] = av1.x;
                    sm[ab + awQ[1]] = av1.y;
                    sm[ab + awQ[2]] = av1.z;
                    sm[ab + awQ[3]] = av1.w;
                    uint4 u0 = make_uint4(f2tf(bv0.x), f2tf(bv0.y), f2tf(bv0.z), f2tf(bv0.w));
                    *(uint4*)(sm + Bnx + bw[0]) = u0;
                    uint4 u1 = make_uint4(f2tf(bv1.x), f2tf(bv1.y), f2tf(bv1.z), f2tf(bv1.w));
                    *(uint4*)(sm + Bnx + bw[1]) = u1;
                }
                av0 = *(const float4*)(aG[2] + ko);
                av1 = *(const float4*)(aG[3] + ko);
                bv0 = *(const float4*)(bG[2] + (size_t)ko * N);
                bv1 = *(const float4*)(bG[3] + (size_t)ko * N);
            }
        }
        if (pf) {
            int ab = Anx + aw0 + 512;
            sm[ab + awQ[0]] = av0.x;
            sm[ab + awQ[1]] = av0.y;
            sm[ab + awQ[2]] = av0.z;
            sm[ab + awQ[3]] = av0.w;
            ab = Anx + aw0 + 768;
            sm[ab + awQ[0]] = av1.x;
            sm[ab + awQ[1]] = av1.y;
            sm[ab + awQ[2]] = av1.z;
            sm[ab + awQ[3]] = av1.w;
            uint4 u0 = make_uint4(f2tf(bv0.x), f2tf(bv0.y), f2tf(bv0.z), f2tf(bv0.w));
            *(uint4*)(sm + Bnx + bw[2]) = u0;
            uint4 u1 = make_uint4(f2tf(bv1.x), f2tf(bv1.y), f2tf(bv1.z), f2tf(bv1.w));
            *(uint4*)(sm + Bnx + bw[3]) = u1;
        }
        __syncthreads();
    }

    // ---- epilogue (GELU layers store tf32-rounded activations) ----
#pragma unroll
    for (int mt = 0; mt < 4; mt++) {
#pragma unroll
        for (int h = 0; h < 2; h++) {
            int rl = wm + mt * 16 + grp + 8 * h;
            if (rl < rows) {
                int orow = m0 + rl;
                if (SCATTER_C) orow = perm[orow];
                float* crow = C + (size_t)orow * N + n0 + wn;
#pragma unroll
                for (int nt = 0; nt < 4; nt++) {
                    int c = nt * 8 + 2 * qid;
                    float x0 = acc[mt][nt][2 * h + 0] + sm[BIAS + wn + c];
                    float x1 = acc[mt][nt][2 * h + 1] + sm[BIAS + wn + c + 1];
                    if (GELU) {
                        x0 = tfr(gelu_f(x0));
                        x1 = tfr(gelu_f(x1));
                    }
                    *(float2*)(crow + c) = make_float2(x0, x1);
                }
            }
        }
    }
}

// ---------------- launcher ----------------
extern "C" void kernel_launch(void* const* d_in, const int* in_sizes, int n_in,
                              void* d_out, int out_size) {
    const int*   genre = (const int*)  d_in[1];
    const float* z     = (const float*)d_in[2];
    const float* mu    = (const float*)d_in[3];
    const float* sigma = (const float*)d_in[4];
    const float* Ws1   = (const float*)d_in[5];
    const float* bs1   = (const float*)d_in[6];
    const float* Ws2   = (const float*)d_in[7];
    const float* bs2   = (const float*)d_in[8];
    const float* We1   = (const float*)d_in[9];
    const float* be1   = (const float*)d_in[10];
    const float* We2   = (const float*)d_in[11];
    const float* be2   = (const float*)d_in[12];
    float* out = (float*)d_out;

    void *px, *ps1, *ps2, *pperm, *ptg, *pts, *ptr_, *ptc;
    cudaGetSymbolAddress(&px,   g_x);
    cudaGetSymbolAddress(&ps1,  g_s1);
    cudaGetSymbolAddress(&ps2,  g_s2);
    cudaGetSymbolAddress(&pperm, g_perm);
    cudaGetSymbolAddress(&ptg,  g_tile_genre);
    cudaGetSymbolAddress(&pts,  g_tile_start);
    cudaGetSymbolAddress(&ptr_, g_tile_rows);
    cudaGetSymbolAddress(&ptc,  g_tile_count);
    float* x  = (float*)px;
    float* s1 = (float*)ps1;
    float* s2 = (float*)ps2;
    const int* perm = (const int*)pperm;
    const int* tg = (const int*)ptg;
    const int* ts = (const int*)pts;
    const int* tr = (const int*)ptr_;
    const int* tc = (const int*)ptc;

    cudaFuncSetAttribute(gemm_tf32<false,false,false,true>,
                         cudaFuncAttributeMaxDynamicSharedMemorySize, SMEM_BYTES);
    cudaFuncSetAttribute(gemm_tf32<true,true,false,true>,
                         cudaFuncAttributeMaxDynamicSharedMemorySize, SMEM_BYTES);
    cudaFuncSetAttribute(gemm_tf32<true,false,true,false>,
                         cudaFuncAttributeMaxDynamicSharedMemorySize, SMEM_BYTES);

    // 1) reparameterized sample (tf32-rounded)
    {
        int total = BSZ * INDIM / 4;
        noise_kernel<<<(total + 255) / 256, 256>>>(
            (const float4*)mu, (const float4*)sigma, (const float4*)z, genre, (float4*)x);
    }
    // 2) grouping
    group_kernel<<<1, 256>>>(genre);

    // 3) shared MLP
    dim3 gs(BSZ / BM, DIM / BN);
    gemm_tf32<false,false,false,true><<<gs, TPB, SMEM_BYTES>>>(
        x, Ws1, bs1, s1, DIM, INDIM, nullptr, nullptr, nullptr, nullptr, nullptr);
    gemm_tf32<false,false,false,true><<<gs, TPB, SMEM_BYTES>>>(
        s1, Ws2, bs2, s2, DIM, DIM, nullptr, nullptr, nullptr, nullptr, nullptr);

    // 4) expert layers
    dim3 ge(MAX_TILES, DIM / BN);
    gemm_tf32<true,true,false,true><<<ge, TPB, SMEM_BYTES>>>(
        s2, We1, be1, s1, DIM, DIM, perm, tg, ts, tr, tc);
    gemm_tf32<true,false,true,false><<<ge, TPB, SMEM_BYTES>>>(
        s1, We2, be2, out, DIM, DIM, perm, tg, ts, tr, tc);
}

// round 8
// speedup vs baseline: 1.0309x; 1.0309x over previous
#include <cuda_runtime.h>
#include <cstdint>
#include <math.h>

// ---------------- problem constants ----------------
#define NGEN 10
#define BSZ  4096
#define INDIM 512
#define DIM  1024
#define MAX_TILES 48

// ---------------- scratch ----------------
__device__ float g_x [BSZ * INDIM];
__device__ float g_s1[BSZ * DIM];
__device__ float g_s2[BSZ * DIM];
__device__ float g_ws1[INDIM * DIM];
__device__ float g_ws2[DIM * DIM];
__device__ float g_we1[NGEN * DIM * DIM];
__device__ float g_we2[NGEN * DIM * DIM];
__device__ int   g_perm[BSZ];
__device__ int   g_tile_genre[MAX_TILES];
__device__ int   g_tile_start[MAX_TILES];
__device__ int   g_tile_rows [MAX_TILES];
__device__ int   g_tile_count;

// ---------------- helpers ----------------
__device__ __forceinline__ unsigned f2tf(float x) {
    unsigned r;
    asm("cvt.rna.tf32.f32 %0, %1;" : "=r"(r) : "f"(x));
    return r;
}
__device__ __forceinline__ float tfr(float x) {
    return __uint_as_float(f2tf(x));
}
__device__ __forceinline__ float gelu_f(float x) {
    return 0.5f * x * (1.0f + erff(x * 0.70710678118654752f));
}

// ---------------- tf32 pre-rounding of weights ----------------
__global__ void round_w(const float4* __restrict__ s, float4* __restrict__ d, int n4) {
    int i = blockIdx.x * blockDim.x + threadIdx.x;
    if (i < n4) {
        float4 v = s[i];
        d[i] = make_float4(tfr(v.x), tfr(v.y), tfr(v.z), tfr(v.w));
    }
}

// ---------------- reparameterized sample (tf32-rounded output) -------------
__global__ void noise_kernel(const float4* __restrict__ mu,
                             const float4* __restrict__ sig,
                             const float4* __restrict__ z,
                             const int* __restrict__ genre,
                             float4* __restrict__ x) {
    const int C4 = INDIM / 4;
    int i = blockIdx.x * blockDim.x + threadIdx.x;
    if (i >= BSZ * C4) return;
    int row = i / C4, c = i - row * C4;
    int g = genre[row];
    float4 m = mu[g * C4 + c];
    float4 s = sig[g * C4 + c];
    float4 zz = z[i];
    float4 o;
    o.x = tfr(m.x + (fabsf(s.x) + 1e-8f) * zz.x);
    o.y = tfr(m.y + (fabsf(s.y) + 1e-8f) * zz.y);
    o.z = tfr(m.z + (fabsf(s.z) + 1e-8f) * zz.z);
    o.w = tfr(m.w + (fabsf(s.w) + 1e-8f) * zz.w);
    x[i] = o;
}

// ---------------- grouping ----------------
__global__ void group_kernel(const int* __restrict__ genre) {
    __shared__ int cnt[256 * NGEN];
    __shared__ int tot[NGEN];
    __shared__ int base[NGEN];
    int t = threadIdx.x;
    const int per = BSZ / 256;

    int lc[NGEN];
#pragma unroll
    for (int g = 0; g < NGEN; g++) lc[g] = 0;
    int gr[per];
    for (int i = 0; i < per; i++) {
        int g = genre[t * per + i];
        gr[i] = g;
        lc[g]++;
    }
    for (int g = 0; g < NGEN; g++) cnt[t * NGEN + g] = lc[g];
    __syncthreads();

    if (t < NGEN) {
        int s = 0;
        for (int tt = 0; tt < 256; tt++) {
            int v = cnt[tt * NGEN + t];
            cnt[tt * NGEN + t] = s;
            s += v;
        }
        tot[t] = s;
    }
    __syncthreads();

    if (t == 0) {
        int off = 0;
        for (int g = 0; g < NGEN; g++) { base[g] = off; off += tot[g]; }
        int T = 0;
        for (int g = 0; g < NGEN; g++) {
            int c = tot[g], s0 = base[g];
            while (c > 0) {
                g_tile_genre[T] = g;
                g_tile_start[T] = s0;
                g_tile_rows[T]  = c < 128 ? c : 128;
                s0 += 128; c -= 128; T++;
            }
        }
        g_tile_count = T;
    }
    __syncthreads();

    int run[NGEN];
#pragma unroll
    for (int g = 0; g < NGEN; g++) run[g] = cnt[t * NGEN + g];
    for (int i = 0; i < per; i++) {
        int g = gr[i];
        int pos = base[g] + run[g]++;
        g_perm[pos] = t * per + i;
    }
}

// ------------- TF32 GEMM: cp.async 3-stage + ldmatrix, 2 CTAs/SM ------------
// Inputs A and B must be pre-rounded to tf32 (raw bits pass through).
constexpr int BM = 128, BN = 128, BK = 32, TPB = 256;
constexpr int A_SW = 36;                     // A smem row stride (words)
constexpr int A_STG = BM * A_SW;             // 4608 words per stage
constexpr int SB = 136;                      // B smem row stride (words)
constexpr int B_STG = BK * SB;               // 4352 words per stage
constexpr int B0W = 3 * A_STG;               // 13824
constexpr int BIAS_W = B0W + 3 * B_STG;      // 26880
constexpr int SMEM_WORDS = BIAS_W + BN;      // 27008
constexpr int SMEM_BYTES = SMEM_WORDS * 4;   // 108032

__device__ __forceinline__ void cp16(uint32_t dst, const float* src) {
    asm volatile("cp.async.cg.shared.global [%0], [%1], 16;"
                 :: "r"(dst), "l"(src) : "memory");
}

template<bool EXPERT, bool GATHER_A, bool SCATTER_C, bool GELU>
__global__ void __launch_bounds__(TPB, 2)
gemm_tf32(const float* __restrict__ A, const float* __restrict__ Bw,
          const float* __restrict__ bias, float* __restrict__ C,
          int N, int K,
          const int* __restrict__ perm,
          const int* __restrict__ tgen, const int* __restrict__ tstart,
          const int* __restrict__ trows, const int* __restrict__ tcnt)
{
    extern __shared__ float sm[];

    int m0, rows, genre = 0;
    if (EXPERT) {
        if ((int)blockIdx.x >= *tcnt) return;
        genre = tgen[blockIdx.x];
        m0    = tstart[blockIdx.x];
        rows  = trows[blockIdx.x];
    } else {
        m0 = blockIdx.x * BM;
        rows = BM;
    }
    const int n0 = blockIdx.y * BN;
    const float* Bsel = EXPERT ? Bw + (size_t)genre * K * N : Bw;
    const float* bsel = EXPERT ? bias + genre * N : bias;

    const int tid = threadIdx.x;
    if (tid < BN) sm[BIAS_W + tid] = bsel[n0 + tid];

    uint32_t smb;
    asm("{ .reg .u64 t; cvta.to.shared.u64 t, %1; cvt.u32.u64 %0, t; }"
        : "=r"(smb) : "l"(sm));

    // ---- A cp.async mapping: 4 chunks/thread (rows row0+32i, 16B seg) ----
    const int row0 = tid >> 3;
    const int seg  = tid & 7;
    const float* aG[4];
    uint32_t awD[4];
#pragma unroll
    for (int i = 0; i < 4; i++) {
        int r = row0 + 32 * i;
        int lrc = r < rows ? r : (rows - 1);
        int src = m0 + lrc;
        if (GATHER_A) src = perm[src];
        aG[i]  = A + (size_t)src * K + seg * 4;
        awD[i] = (uint32_t)(r * A_SW + seg * 4) * 4;
    }
    // ---- B cp.async mapping: 4 chunks/thread ----
    const float* bG[4];
    uint32_t bwD[4];
#pragma unroll
    for (int j = 0; j < 4; j++) {
        int v = tid + TPB * j;
        int kB = v >> 5, n4 = v & 31;
        bG[j]  = Bsel + (size_t)kB * N + n0 + n4 * 4;
        bwD[j] = (uint32_t)(kB * SB + n4 * 4) * 4;
    }

    const int nk = K / BK;

    auto issue = [&](int kt) {
        const uint32_t as = smb + (uint32_t)((kt % 3) * A_STG) * 4;
        const uint32_t bs = smb + (uint32_t)(B0W + (kt % 3) * B_STG) * 4;
        const int ko = kt * BK;
#pragma unroll
        for (int i = 0; i < 4; i++) cp16(as + awD[i], aG[i] + ko);
#pragma unroll
        for (int j = 0; j < 4; j++) cp16(bs + bwD[j], bG[j] + (size_t)ko * N);
        asm volatile("cp.async.commit_group;" ::: "memory");
    };

    issue(0);
    issue(1);
    asm volatile("cp.async.wait_group 1;" ::: "memory");
    __syncthreads();

    // ---- compute mapping: 8 warps, warp tile 64x32 ----
    const int wid = tid >> 5, lane = tid & 31;
    const int wm = (wid >> 2) * 64;
    const int wn = (wid & 3) * 32;
    const int grp = lane >> 2, qid = lane & 3;
    const int mtBase = wm >> 4;              // 0 or 4
    // ldmatrix per-lane byte offset within a stage
    const uint32_t lmOff = (uint32_t)(((lane & 15) * A_SW + (lane >> 4) * 4) * 4);

    bool mAct[4];
#pragma unroll
    for (int mt = 0; mt < 4; mt++) mAct[mt] = (wm + mt * 16) < rows;

    float acc[4][4][4];
#pragma unroll
    for (int i = 0; i < 4; i++)
#pragma unroll
        for (int j = 0; j < 4; j++)
#pragma unroll
            for (int q = 0; q < 4; q++) acc[i][j][q] = 0.f;

    for (int kt = 0; kt < nk; kt++) {
        if (kt + 2 < nk) issue(kt + 2);

        const uint32_t asB = smb + (uint32_t)((kt % 3) * A_STG) * 4;
        const int bsW = B0W + (kt % 3) * B_STG;
#pragma unroll
        for (int ks = 0; ks < 4; ks++) {
            uint32_t a[4][4];
#pragma unroll
            for (int mt = 0; mt < 4; mt++) {
                if (mAct[mt]) {
                    uint32_t ad = asB + lmOff + (uint32_t)((mtBase + mt) * 16 * A_SW * 4 + ks * 32);
                    asm volatile(
                        "ldmatrix.sync.aligned.m8n8.x4.shared.b16 {%0,%1,%2,%3}, [%4];"
                        : "=r"(a[mt][0]), "=r"(a[mt][1]), "=r"(a[mt][2]), "=r"(a[mt][3])
                        : "r"(ad));
                }
            }
            unsigned bfr[4][2];
#pragma unroll
            for (int nt = 0; nt < 4; nt++) {
                int col = wn + nt * 8 + grp;
                bfr[nt][0] = __float_as_uint(sm[bsW + (ks * 8 + qid) * SB + col]);
                bfr[nt][1] = __float_as_uint(sm[bsW + (ks * 8 + qid + 4) * SB + col]);
            }
#pragma unroll
            for (int mt = 0; mt < 4; mt++) {
                if (!mAct[mt]) continue;
#pragma unroll
                for (int nt = 0; nt < 4; nt++) {
                    float* d = acc[mt][nt];
                    asm volatile(
                        "mma.sync.aligned.m16n8k8.row.col.f32.tf32.tf32.f32 "
                        "{%0,%1,%2,%3},{%4,%5,%6,%7},{%8,%9},{%0,%1,%2,%3};\n"
                        : "+f"(d[0]), "+f"(d[1]), "+f"(d[2]), "+f"(d[3])
                        : "r"(a[mt][0]), "r"(a[mt][1]), "r"(a[mt][2]), "r"(a[mt][3]),
                          "r"(bfr[nt][0]), "r"(bfr[nt][1]));
                }
            }
        }
        if (kt + 1 < nk) {
            if (kt + 2 < nk) {
                asm volatile("cp.async.wait_group 1;" ::: "memory");
            } else {
                asm volatile("cp.async.wait_group 0;" ::: "memory");
            }
        }
        __syncthreads();
    }

    // ---- epilogue ----
#pragma unroll
    for (int mt = 0; mt < 4; mt++) {
#pragma unroll
        for (int h = 0; h < 2; h++) {
            int rl = wm + mt * 16 + grp + 8 * h;
            if (rl < rows) {
                int orow = m0 + rl;
                if (SCATTER_C) orow = perm[orow];
                float* crow = C + (size_t)orow * N + n0 + wn;
#pragma unroll
                for (int nt = 0; nt < 4; nt++) {
                    int c = nt * 8 + 2 * qid;
                    float x0 = acc[mt][nt][2 * h + 0] + sm[BIAS_W + wn + c];
                    float x1 = acc[mt][nt][2 * h + 1] + sm[BIAS_W + wn + c + 1];
                    if (GELU) {
                        x0 = tfr(gelu_f(x0));
                        x1 = tfr(gelu_f(x1));
                    }
                    *(float2*)(crow + c) = make_float2(x0, x1);
                }
            }
        }
    }
}

// ---------------- launcher ----------------
extern "C" void kernel_launch(void* const* d_in, const int* in_sizes, int n_in,
                              void* d_out, int out_size) {
    const int*   genre = (const int*)  d_in[1];
    const float* z     = (const float*)d_in[2];
    const float* mu    = (const float*)d_in[3];
    const float* sigma = (const float*)d_in[4];
    const float* Ws1   = (const float*)d_in[5];
    const float* bs1   = (const float*)d_in[6];
    const float* Ws2   = (const float*)d_in[7];
    const float* bs2   = (const float*)d_in[8];
    const float* We1   = (const float*)d_in[9];
    const float* be1   = (const float*)d_in[10];
    const float* We2   = (const float*)d_in[11];
    const float* be2   = (const float*)d_in[12];
    float* out = (float*)d_out;

    void *px, *ps1, *ps2, *pw1, *pw2, *pe1, *pe2, *pperm, *ptg, *pts, *ptr_, *ptc;
    cudaGetSymbolAddress(&px,   g_x);
    cudaGetSymbolAddress(&ps1,  g_s1);
    cudaGetSymbolAddress(&ps2,  g_s2);
    cudaGetSymbolAddress(&pw1,  g_ws1);
    cudaGetSymbolAddress(&pw2,  g_ws2);
    cudaGetSymbolAddress(&pe1,  g_we1);
    cudaGetSymbolAddress(&pe2,  g_we2);
    cudaGetSymbolAddress(&pperm, g_perm);
    cudaGetSymbolAddress(&ptg,  g_tile_genre);
    cudaGetSymbolAddress(&pts,  g_tile_start);
    cudaGetSymbolAddress(&ptr_, g_tile_rows);
    cudaGetSymbolAddress(&ptc,  g_tile_count);
    float* x   = (float*)px;
    float* s1  = (float*)ps1;
    float* s2  = (float*)ps2;
    float* ws1 = (float*)pw1;
    float* ws2 = (float*)pw2;
    float* we1 = (float*)pe1;
    float* we2 = (float*)pe2;
    const int* perm = (const int*)pperm;
    const int* tg = (const int*)ptg;
    const int* ts = (const int*)pts;
    const int* tr = (const int*)ptr_;
    const int* tc = (const int*)ptc;

    cudaFuncSetAttribute(gemm_tf32<false,false,false,true>,
                         cudaFuncAttributeMaxDynamicSharedMemorySize, SMEM_BYTES);
    cudaFuncSetAttribute(gemm_tf32<true,true,false,true>,
                         cudaFuncAttributeMaxDynamicSharedMemorySize, SMEM_BYTES);
    cudaFuncSetAttribute(gemm_tf32<true,false,true,false>,
                         cudaFuncAttributeMaxDynamicSharedMemorySize, SMEM_BYTES);

    // 0) pre-round weights to tf32 (identity for already-tf32 values)
    round_w<<<(INDIM * DIM / 4 + 255) / 256, 256>>>((const float4*)Ws1, (float4*)ws1, INDIM * DIM / 4);
    round_w<<<(DIM * DIM / 4 + 255) / 256, 256>>>((const float4*)Ws2, (float4*)ws2, DIM * DIM / 4);
    round_w<<<(NGEN * DIM * DIM / 4 + 255) / 256, 256>>>((const float4*)We1, (float4*)we1, NGEN * DIM * DIM / 4);
    round_w<<<(NGEN * DIM * DIM / 4 + 255) / 256, 256>>>((const float4*)We2, (float4*)we2, NGEN * DIM * DIM / 4);

    // 1) reparameterized sample (tf32-rounded)
    {
        int total = BSZ * INDIM / 4;
        noise_kernel<<<(total + 255) / 256, 256>>>(
            (const float4*)mu, (const float4*)sigma, (const float4*)z, genre, (float4*)x);
    }
    // 2) grouping
    group_kernel<<<1, 256>>>(genre);

    // 3) shared MLP
    dim3 gs(BSZ / BM, DIM / BN);
    gemm_tf32<false,false,false,true><<<gs, TPB, SMEM_BYTES>>>(
        x, ws1, bs1, s1, DIM, INDIM, nullptr, nullptr, nullptr, nullptr, nullptr);
    gemm_tf32<false,false,false,true><<<gs, TPB, SMEM_BYTES>>>(
        s1, ws2, bs2, s2, DIM, DIM, nullptr, nullptr, nullptr, nullptr, nullptr);

    // 4) expert layers
    dim3 ge(MAX_TILES, DIM / BN);
    gemm_tf32<true,true,false,true><<<ge, TPB, SMEM_BYTES>>>(
        s2, we1, be1, s1, DIM, DIM, perm, tg, ts, tr, tc);
    gemm_tf32<true,false,true,false><<<ge, TPB, SMEM_BYTES>>>(
        s1, we2, be2, out, DIM, DIM, perm, tg, ts, tr, tc);
}